// round 16
// baseline (speedup 1.0000x reference)
#include <cuda_runtime.h>
#include <cuda_fp16.h>
#include <math.h>
#include <cstdint>

#define NT 4096
#define NS 2048
#define NV 1024
#define H 256
#define NH 4
#define DH 64
#define E1 65536
#define E2 16384
#define E3 32768
#define ETOT (2*E1 + E2 + E3)
#define KBIG 1280   // [agg0|agg1|agg2|agg3|x_term(direct)] blocks of 256

// ---------------- scratch (static device globals; no allocation) ----------------
__device__ float g_Abig[NT * KBIG];
__device__ float g_cnt[4 * NT];
__device__ float g_Wbig[H * KBIG];
__device__ float g_bsum[H];
__device__ float g_pre[NT * H];
__device__ float g_tout[NT * H];
__device__ float g_qkv[NT * 3 * H];
__device__ float g_ctx[NT * H];
__device__ float g_attn[NT * H];

// ---------------- fp16 mma.sync helpers ----------------
__device__ __forceinline__ void mma_f16(float* c, uint32_t a0, uint32_t a1, uint32_t a2, uint32_t a3,
                                        uint32_t b0, uint32_t b1)
{
    asm volatile("mma.sync.aligned.m16n8k16.row.col.f32.f16.f16.f32 "
                 "{%0,%1,%2,%3},{%4,%5,%6,%7},{%8,%9},{%0,%1,%2,%3};"
                 : "+f"(c[0]), "+f"(c[1]), "+f"(c[2]), "+f"(c[3])
                 : "r"(a0), "r"(a1), "r"(a2), "r"(a3), "r"(b0), "r"(b1));
}
__device__ __forceinline__ uint32_t h2(float a, float b) {
    __half2 h = __floats2half2_rn(a, b);
    return *(uint32_t*)&h;
}
__device__ __forceinline__ float ex2f(float x) {
    asm("ex2.approx.ftz.f32 %0, %0;" : "+f"(x));
    return x;
}
// Convert 16 consecutive k-floats (one k16 group) into 8 permuted half2 u32:
// pair p_i = (f2i, f2i+1); layout (p0,p4,p1,p5,p2,p6,p3,p7) so that a uint2 at
// offset 2*tig yields {klo(2tig,2tig+1), khi(2tig+8,2tig+9)}.
__device__ __forceinline__ void cvt_store_group(uint32_t* dst, float4 v0, float4 v1,
                                                float4 v2, float4 v3, float scl)
{
    uint4 u0, u1;
    u0.x = h2(v0.x * scl, v0.y * scl); u0.y = h2(v2.x * scl, v2.y * scl);
    u0.z = h2(v0.z * scl, v0.w * scl); u0.w = h2(v2.z * scl, v2.w * scl);
    u1.x = h2(v1.x * scl, v1.y * scl); u1.y = h2(v3.x * scl, v3.y * scl);
    u1.z = h2(v1.z * scl, v1.w * scl); u1.w = h2(v3.z * scl, v3.w * scl);
    *(uint4*)dst = u0;
    *(uint4*)(dst + 4) = u1;
}

// ---------------- fused prep: Wbig/bsum + A_big agg-zero + cnt zero ----------------
__global__ void prep_init_kernel(const float* __restrict__ Wl0, const float* __restrict__ Wl1,
                                 const float* __restrict__ Wl2, const float* __restrict__ Wl3,
                                 const float* __restrict__ Wr0, const float* __restrict__ Wr1,
                                 const float* __restrict__ Wr2, const float* __restrict__ Wr3,
                                 const float* __restrict__ bl0, const float* __restrict__ bl1,
                                 const float* __restrict__ bl2, const float* __restrict__ bl3)
{
    int idx = blockIdx.x * blockDim.x + threadIdx.x;
    if (idx < NT * 256) {   // zero the 4 agg blocks (first 1024 cols) only
        int n = idx >> 8, c4 = idx & 255;
        ((float4*)g_Abig)[n * (KBIG / 4) + c4] = make_float4(0.f, 0.f, 0.f, 0.f);
    }
    if (idx < H * KBIG) {
        int h = idx / KBIG, c = idx % KBIG;
        int r = c >> 8, k = c & 255;
        int wi = h * H + k;
        float v;
        if (r == 0)      v = Wl0[wi];
        else if (r == 1) v = Wl1[wi];
        else if (r == 2) v = Wl2[wi];
        else if (r == 3) v = Wl3[wi];
        else             v = Wr0[wi] + Wr1[wi] + Wr2[wi] + Wr3[wi];
        g_Wbig[idx] = v;
    }
    if (idx < 4 * NT) g_cnt[idx] = 0.f;
    if (idx < H) g_bsum[idx] = bl0[idx] + bl1[idx] + bl2[idx] + bl3[idx];
}

// ---------------- scatter-add messages + degree counts (32 thr/edge, MLP=2) ----------------
__global__ void scatter_kernel(const float* __restrict__ xt, const float* __restrict__ xs,
                               const float* __restrict__ xv,
                               const int* __restrict__ ha_src, const int* __restrict__ ha_dst,
                               const int* __restrict__ so_src, const int* __restrict__ so_dst,
                               const int* __restrict__ vo_src, const int* __restrict__ vo_dst)
{
    int idx = blockIdx.x * blockDim.x + threadIdx.x;
    if (idx >= ETOT * 32) return;
    int e = idx >> 5, j = idx & 31;
    int r, s, d; const float* x;
    if (e < E1)               { r = 0; s = ha_dst[e];            d = ha_src[e];            x = xt; }
    else if (e < 2 * E1)      { int q = e - E1;          r = 1; s = ha_src[q]; d = ha_dst[q]; x = xt; }
    else if (e < 2 * E1 + E2) { int q = e - 2 * E1;      r = 2; s = so_dst[q]; d = so_src[q]; x = xs; }
    else                      { int q = e - 2 * E1 - E2; r = 3; s = vo_src[q]; d = vo_dst[q]; x = xv; }
    const float4* src = (const float4*)(x + (size_t)s * H);
    float4 v0 = src[j];
    float4 v1 = src[j + 32];
    float* p = g_Abig + (size_t)d * KBIG + r * H + j * 4;
    asm volatile("red.global.add.v4.f32 [%0], {%1,%2,%3,%4};"
                 :: "l"(p), "f"(v0.x), "f"(v0.y), "f"(v0.z), "f"(v0.w) : "memory");
    asm volatile("red.global.add.v4.f32 [%0], {%1,%2,%3,%4};"
                 :: "l"(p + 128), "f"(v1.x), "f"(v1.y), "f"(v1.z), "f"(v1.w) : "memory");
    if (j == 0) atomicAdd(&g_cnt[r * NT + d], 1.f);
}

// ================= fp16 tensor-core GEMM (3-stage smem pipeline, templated N-tile) =================
// C[M,N] = A[M,K] @ W[N,K]^T + bias (+epilogue). cnt!=null => conv mode:
// scale agg chunks (kc<32) by 1/max(cnt,1); chunks >=32 read directly from xterm.
#define RS 24
template<int NTILE>
__global__ __launch_bounds__(256, 1)
void gemm_tc_kernel(const float* __restrict__ A, const float* __restrict__ W,
                    const float* __restrict__ bias, const float* __restrict__ resid,
                    const float* __restrict__ cnt, const float* __restrict__ xterm,
                    float* __restrict__ C, int M, int N, int K, int mode)
{
    extern __shared__ uint32_t S[];
    constexpr int NW = NTILE / 8;
    constexpr int STG = (128 + NTILE) * RS;
    int tid = threadIdx.x;
    int lane = tid & 31, wid = tid >> 5;
    int g = lane >> 2, tig = lane & 3;
    int rb = blockIdx.y * 128;
    int cb = blockIdx.x * NTILE;

    int aRow = tid >> 1;            // A: 2 threads per row, 16 cols (one group) each
    int aGrp = tid & 1;

    float inv[4] = {1.f, 1.f, 1.f, 1.f};
    if (cnt) {
#pragma unroll
        for (int r = 0; r < 4; r++)
            inv[r] = 1.f / fmaxf(cnt[r * NT + rb + aRow], 1.f);
    }

    float4 aR[4], wR[4];
    const float* Ap = A + (size_t)(rb + aRow) * K + aGrp * 16;
    const float* Axt = xterm ? (xterm + (size_t)(rb + aRow) * H + aGrp * 16) : nullptr;

    int wRow, wSub;
    const float* Wp;
    if (NTILE == 128) {
        wRow = tid >> 1; wSub = tid & 1;
        Wp = W + (size_t)(cb + wRow) * K + wSub * 16;
    } else {
        wRow = tid >> 2; wSub = tid & 3;
        Wp = W + (size_t)(cb + wRow) * K + wSub * 8;
    }

    auto loadC = [&](int kc) {
        const float* Ap2 = (xterm && kc >= 32) ? (Axt + (kc - 32) * 32) : (Ap + kc * 32);
        const float* Wp2 = Wp + kc * 32;
#pragma unroll
        for (int j = 0; j < 4; j++) aR[j] = *(const float4*)(Ap2 + j * 4);
        if (NTILE == 128) {
#pragma unroll
            for (int j = 0; j < 4; j++) wR[j] = *(const float4*)(Wp2 + j * 4);
        } else {
#pragma unroll
            for (int j = 0; j < 2; j++) wR[j] = *(const float4*)(Wp2 + j * 4);
        }
    };
    auto storeC = [&](int kc, int stg) {
        uint32_t* As = S + stg * STG;
        uint32_t* Ws = As + 128 * RS;
        float sc = (cnt && kc < 32) ? inv[kc >> 3] : 1.f;
        cvt_store_group(As + aRow * RS + aGrp * 8, aR[0], aR[1], aR[2], aR[3], sc);
        if (NTILE == 128) {
            cvt_store_group(Ws + wRow * RS + wSub * 8, wR[0], wR[1], wR[2], wR[3], 1.f);
        } else {
            uint32_t* wb = Ws + wRow * RS + (wSub >> 1) * 8 + (wSub & 1);
            wb[0] = h2(wR[0].x, wR[0].y);
            wb[2] = h2(wR[0].z, wR[0].w);
            wb[4] = h2(wR[1].x, wR[1].y);
            wb[6] = h2(wR[1].z, wR[1].w);
        }
    };

    float acc[NW][4];
#pragma unroll
    for (int n = 0; n < NW; n++)
#pragma unroll
        for (int i = 0; i < 4; i++) acc[n][i] = 0.f;

    int nchunk = K >> 5;
    loadC(0); storeC(0, 0);
    loadC(1); storeC(1, 1);
    __syncthreads();

    int r0 = wid * 16 + g;
    for (int kc = 0; kc < nchunk; kc++) {
        int cur = kc % 3;
        bool pf = (kc + 2) < nchunk;
        if (pf) loadC(kc + 2);

        const uint32_t* As = S + cur * STG;
        const uint32_t* Ws = As + 128 * RS;
#pragma unroll
        for (int ks = 0; ks < 2; ks++) {
            uint2 aA = *(uint2*)&As[r0 * RS + ks * 8 + 2 * tig];
            uint2 aB = *(uint2*)&As[(r0 + 8) * RS + ks * 8 + 2 * tig];
#pragma unroll
            for (int n = 0; n < NW; n++) {
                uint2 b = *(uint2*)&Ws[(n * 8 + g) * RS + ks * 8 + 2 * tig];
                mma_f16(acc[n], aA.x, aB.x, aA.y, aB.y, b.x, b.y);
            }
        }
        __syncthreads();
        if (pf) storeC(kc + 2, (kc + 2) % 3);
    }

    // epilogue (fp32)
    int gr0 = rb + wid * 16 + g;
#pragma unroll
    for (int n = 0; n < NW; n++) {
        int col = cb + n * 8 + 2 * tig;
        float2 bv = *(const float2*)(bias + col);
        float2 v0 = make_float2(acc[n][0] + bv.x, acc[n][1] + bv.y);
        float2 v1 = make_float2(acc[n][2] + bv.x, acc[n][3] + bv.y);
        if (mode == 2) {
            v0.x = fmaxf(v0.x, 0.f); v0.y = fmaxf(v0.y, 0.f);
            v1.x = fmaxf(v1.x, 0.f); v1.y = fmaxf(v1.y, 0.f);
        }
        if (mode >= 1) {
            float2 r0v = *(const float2*)(resid + (size_t)gr0 * N + col);
            float2 r1v = *(const float2*)(resid + (size_t)(gr0 + 8) * N + col);
            v0.x += r0v.x; v0.y += r0v.y; v1.x += r1v.x; v1.y += r1v.y;
        }
        *(float2*)(C + (size_t)gr0 * N + col) = v0;
        *(float2*)(C + (size_t)(gr0 + 8) * N + col) = v1;
    }
}

// ---------------- layernorm ----------------
__global__ __launch_bounds__(256)
void ln_kernel(const float* __restrict__ pre, const float* __restrict__ gam,
               const float* __restrict__ bet, float* __restrict__ out)
{
    int row = blockIdx.x * 8 + (threadIdx.x >> 5);
    int lane = threadIdx.x & 31;
    const float* p = pre + (size_t)row * H + lane * 8;
    float4 a = *(const float4*)p;
    float4 b = *(const float4*)(p + 4);
    float s = a.x + a.y + a.z + a.w + b.x + b.y + b.z + b.w;
#pragma unroll
    for (int off = 16; off; off >>= 1) s += __shfl_xor_sync(0xffffffffu, s, off);
    float mu = s * (1.f / H);
    float dx[8] = {a.x - mu, a.y - mu, a.z - mu, a.w - mu, b.x - mu, b.y - mu, b.z - mu, b.w - mu};
    float vs = 0.f;
#pragma unroll
    for (int i = 0; i < 8; i++) vs += dx[i] * dx[i];
#pragma unroll
    for (int off = 16; off; off >>= 1) vs += __shfl_xor_sync(0xffffffffu, vs, off);
    float rstd = rsqrtf(vs * (1.f / H) + 1e-5f);
    float4 g0 = *(const float4*)(gam + lane * 8);
    float4 g1 = *(const float4*)(gam + lane * 8 + 4);
    float4 b0 = *(const float4*)(bet + lane * 8);
    float4 b1 = *(const float4*)(bet + lane * 8 + 4);
    float4 o0 = make_float4(dx[0] * rstd * g0.x + b0.x, dx[1] * rstd * g0.y + b0.y,
                            dx[2] * rstd * g0.z + b0.z, dx[3] * rstd * g0.w + b0.w);
    float4 o1 = make_float4(dx[4] * rstd * g1.x + b1.x, dx[5] * rstd * g1.y + b1.y,
                            dx[6] * rstd * g1.z + b1.z, dx[7] * rstd * g1.w + b1.w);
    float* q = out + (size_t)row * H + lane * 8;
    *(float4*)q = o0;
    *(float4*)(q + 4) = o1;
}

// ================= fp16 mma.sync flash attention (3-stage KV pipeline) =================
// CTA: 256 threads (8 warps), 128 q-rows, one head. Key tiles of 64, one sync/tile.
// Q pre-scaled by log2(e)/8 so S is in log2 domain; P = ex2(S). l computed by the
// tensor core: VT has a 9th n-group whose col 0 is a ones-row -> O[8] = row sums of P.
#define QS 40
#define QFL (128 * QS)
#define KVSTG ((64 + 72) * QS)     // 64 K rows + 72 VT rows (64 d + ones/zero pad)
#define ATTN_SMEM_BYTES ((QFL + 3 * KVSTG) * 4)

__global__ __launch_bounds__(256, 1)
void attn_tc_kernel(const float* __restrict__ qkv, float* __restrict__ ctx)
{
    extern __shared__ __align__(16) uint32_t sm[];
    uint32_t* Qs = sm;

    int tid = threadIdx.x;
    int lane = tid & 31, wid = tid >> 5;
    int g = lane >> 2, tig = lane & 3;
    int h = blockIdx.y;
    int q0 = blockIdx.x * 128;

    // ---- load Q (once), scaled by log2(e)/8 ----
    {
        int qRow = tid >> 1;
        int qh = tid & 1;
        const float* qr = qkv + (size_t)(q0 + qRow) * 768 + h * 64 + qh * 32;
        float4 v0 = *(const float4*)(qr + 0),  v1 = *(const float4*)(qr + 4);
        float4 v2 = *(const float4*)(qr + 8),  v3 = *(const float4*)(qr + 12);
        float4 v4 = *(const float4*)(qr + 16), v5 = *(const float4*)(qr + 20);
        float4 v6 = *(const float4*)(qr + 24), v7 = *(const float4*)(qr + 28);
        const float QSC = 0.18033688011112042f;   // log2(e)/8
        cvt_store_group(Qs + qRow * QS + qh * 16,     v0, v1, v2, v3, QSC);
        cvt_store_group(Qs + qRow * QS + qh * 16 + 8, v4, v5, v6, v7, QSC);
    }

    // ---- init VT pad rows (64..71) for all 3 stages: row 64 = ones, rest zero ----
    // VT region starts at stage + 64*QS (after Ks); its rows 64..71 start at
    // stage + 64*QS + 64*QS = stage + 128*QS.
    for (int i = tid; i < 960; i += 256) {
        int stg = i / 320, rr = i % 320;
        uint32_t* vt = sm + QFL + stg * KVSTG + 128 * QS;
        vt[rr] = (rr < QS) ? 0x3C003C00u : 0u;
    }

    // K/V: 4 threads per K row, 16 cols (one group) each.
    int kRow = tid >> 2;
    int kSub = tid & 3;
    int pk = kRow >> 1;
    int wp = ((pk & 3) << 1) | ((pk >> 2) & 1);
    int hp = (kRow >> 4) * 16 + wp * 2 + (kRow & 1);
    float4 Kbuf[4], Vbuf[4];

    auto loadKV = [&](int kt) {
        const float* kp = qkv + (size_t)(kt * 64 + kRow) * 768 + 256 + h * 64 + kSub * 16;
#pragma unroll
        for (int j = 0; j < 4; j++) Kbuf[j] = *(const float4*)(kp + j * 4);
#pragma unroll
        for (int j = 0; j < 4; j++) Vbuf[j] = *(const float4*)(kp + 256 + j * 4);
    };
    auto storeKV = [&](int stg) {
        uint32_t* Ks = sm + QFL + stg * KVSTG;
        cvt_store_group(Ks + kRow * QS + kSub * 8, Kbuf[0], Kbuf[1], Kbuf[2], Kbuf[3], 1.f);
        __half* VTh = (__half*)(Ks + 64 * QS);
#pragma unroll
        for (int j = 0; j < 4; j++) {
            int d = kSub * 16 + j * 4;
            VTh[(d + 0) * (QS * 2) + hp] = __float2half_rn(Vbuf[j].x);
            VTh[(d + 1) * (QS * 2) + hp] = __float2half_rn(Vbuf[j].y);
            VTh[(d + 2) * (QS * 2) + hp] = __float2half_rn(Vbuf[j].z);
            VTh[(d + 3) * (QS * 2) + hp] = __float2half_rn(Vbuf[j].w);
        }
    };

    float O[9][4];
#pragma unroll
    for (int n = 0; n < 9; n++)
#pragma unroll
        for (int i = 0; i < 4; i++) O[n][i] = 0.f;

    loadKV(0); storeKV(0);
    loadKV(1); storeKV(1);
    __syncthreads();

    int qr = wid * 16 + g;
    for (int kt = 0; kt < 64; kt++) {
        int cur = kt % 3;
        bool pf = (kt + 2) < 64;
        if (pf) loadKV(kt + 2);

        const uint32_t* Ks = sm + QFL + cur * KVSTG;
        const uint32_t* VT = Ks + 64 * QS;

        float c[8][4];
#pragma unroll
        for (int n = 0; n < 8; n++)
#pragma unroll
            for (int i = 0; i < 4; i++) c[n][i] = 0.f;

        // S(log2 domain) = (Q*log2e/8) K^T over d=64 (4 k16 steps)
#pragma unroll
        for (int ks = 0; ks < 4; ks++) {
            uint2 qa = *(uint2*)&Qs[qr * QS + ks * 8 + 2 * tig];
            uint2 qb = *(uint2*)&Qs[(qr + 8) * QS + ks * 8 + 2 * tig];
#pragma unroll
            for (int n = 0; n < 8; n++) {
                uint2 kb = *(uint2*)&Ks[(n * 8 + g) * QS + ks * 8 + 2 * tig];
                mma_f16(c[n], qa.x, qb.x, qa.y, qb.y, kb.x, kb.y);
            }
        }

        // P = 2^S (clamped), pack to fp16 fragment, O += P V ; O[8] accumulates l.
#pragma unroll
        for (int j = 0; j < 4; j++) {
            float p00 = ex2f(fminf(c[2 * j][0], 15.5f));
            float p01 = ex2f(fminf(c[2 * j][1], 15.5f));
            float p02 = ex2f(fminf(c[2 * j][2], 15.5f));
            float p03 = ex2f(fminf(c[2 * j][3], 15.5f));
            float p10 = ex2f(fminf(c[2 * j + 1][0], 15.5f));
            float p11 = ex2f(fminf(c[2 * j + 1][1], 15.5f));
            float p12 = ex2f(fminf(c[2 * j + 1][2], 15.5f));
            float p13 = ex2f(fminf(c[2 * j + 1][3], 15.5f));
            uint32_t a0 = h2(p00, p01);
            uint32_t a1 = h2(p02, p03);
            uint32_t a2 = h2(p10, p11);
            uint32_t a3 = h2(p12, p13);
#pragma unroll
            for (int dn = 0; dn < 9; dn++) {
                uint2 vb = *(uint2*)&VT[(dn * 8 + g) * QS + j * 8 + 2 * tig];
                mma_f16(O[dn], a0, a1, a2, a3, vb.x, vb.y);
            }
        }
        __syncthreads();
        if (pf) storeKV((kt + 2) % 3);
    }

    // l lives in O[8][0]/O[8][2] of lanes with tig==0 (col 0 of the ones group)
    float l0 = __shfl_sync(0xffffffffu, O[8][0], lane & ~3);
    float l1 = __shfl_sync(0xffffffffu, O[8][2], lane & ~3);
    float inv0 = 1.f / l0;
    float inv1 = 1.f / l1;

    int r0 = q0 + wid * 16 + g;
#pragma unroll
    for (int dn = 0; dn < 8; dn++) {
        int col = h * 64 + dn * 8 + 2 * tig;
        float2 v0 = make_float2(O[dn][0] * inv0, O[dn][1] * inv0);
        float2 v1 = make_float2(O[dn][2] * inv1, O[dn][3] * inv1);
        *(float2*)(ctx + (size_t)r0 * 256 + col) = v0;
        *(float2*)(ctx + (size_t)(r0 + 8) * 256 + col) = v1;
    }
}

// ---------------- launch ----------------
#define GEMM_SMEM_64  (3 * (128 + 64) * RS * 4)
#define GEMM_SMEM_128 (3 * (128 + 128) * RS * 4)

extern "C" void kernel_launch(void* const* d_in, const int* in_sizes, int n_in,
                              void* d_out, int out_size)
{
    (void)in_sizes; (void)n_in; (void)out_size;
    const float* x_term    = (const float*)d_in[0];
    const float* x_symbol  = (const float*)d_in[1];
    const float* x_var     = (const float*)d_in[2];
    const int*   ha_src    = (const int*)d_in[3];
    const int*   ha_dst    = (const int*)d_in[4];
    const int*   so_src    = (const int*)d_in[5];
    const int*   so_dst    = (const int*)d_in[6];
    const int*   vo_src    = (const int*)d_in[7];
    const int*   vo_dst    = (const int*)d_in[8];
    const float* Wl_rha    = (const float*)d_in[9];
    const float* bl_rha    = (const float*)d_in[10];
    const float* Wr_rha    = (const float*)d_in[11];
    const float* Wl_ha     = (const float*)d_in[12];
    const float* bl_ha     = (const float*)d_in[13];
    const float* Wr_ha     = (const float*)d_in[14];
    const float* Wl_rsym   = (const float*)d_in[15];
    const float* bl_rsym   = (const float*)d_in[16];
    const float* Wr_rsym   = (const float*)d_in[17];
    const float* Wl_var    = (const float*)d_in[18];
    const float* bl_var    = (const float*)d_in[19];
    const float* Wr_var    = (const float*)d_in[20];
    const float* ln_g      = (const float*)d_in[21];
    const float* ln_b      = (const float*)d_in[22];
    const float* in_proj_w = (const float*)d_in[23];
    const float* in_proj_b = (const float*)d_in[24];
    const float* out_proj_w= (const float*)d_in[25];
    const float* out_proj_b= (const float*)d_in[26];
    const float* post_w    = (const float*)d_in[27];
    const float* post_b    = (const float*)d_in[28];
    float* out = (float*)d_out;

    cudaFuncSetAttribute(attn_tc_kernel, cudaFuncAttributeMaxDynamicSharedMemorySize, ATTN_SMEM_BYTES);
    cudaFuncSetAttribute(gemm_tc_kernel<64>, cudaFuncAttributeMaxDynamicSharedMemorySize, GEMM_SMEM_64);
    cudaFuncSetAttribute(gemm_tc_kernel<128>, cudaFuncAttributeMaxDynamicSharedMemorySize, GEMM_SMEM_128);

    float *pAbig, *pWbig, *pbsum, *pcnt, *ppre, *ptout, *pqkv, *pctx, *pattn;
    cudaGetSymbolAddress((void**)&pAbig, g_Abig);
    cudaGetSymbolAddress((void**)&pWbig, g_Wbig);
    cudaGetSymbolAddress((void**)&pbsum, g_bsum);
    cudaGetSymbolAddress((void**)&pcnt,  g_cnt);
    cudaGetSymbolAddress((void**)&ppre,  g_pre);
    cudaGetSymbolAddress((void**)&ptout, g_tout);
    cudaGetSymbolAddress((void**)&pqkv,  g_qkv);
    cudaGetSymbolAddress((void**)&pctx,  g_ctx);
    cudaGetSymbolAddress((void**)&pattn, g_attn);

    prep_init_kernel<<<(NT * 256 + 255) / 256, 256>>>(Wl_rha, Wl_ha, Wl_rsym, Wl_var,
                                                      Wr_rha, Wr_ha, Wr_rsym, Wr_var,
                                                      bl_rha, bl_ha, bl_rsym, bl_var);
    scatter_kernel<<<(ETOT * 32 + 255) / 256, 256>>>(x_term, x_symbol, x_var,
                                                     ha_src, ha_dst, so_src, so_dst, vo_src, vo_dst);

    // conv = (A_big * (1/cnt per block)) @ Wbig^T + bsum + x_term  -> g_pre
    gemm_tc_kernel<64><<<dim3(H / 64, NT / 128), 256, GEMM_SMEM_64>>>(
        pAbig, pWbig, pbsum, x_term, pcnt, x_term, ppre, NT, H, KBIG, 1);
    ln_kernel<<<NT / 8, 256>>>(ppre, ln_g, ln_b, ptout);
    // qkv (wide N-tile: 192 CTAs = 1.3 waves)
    gemm_tc_kernel<128><<<dim3(3 * H / 128, NT / 128), 256, GEMM_SMEM_128>>>(
        ptout, in_proj_w, in_proj_b, nullptr, nullptr, nullptr, pqkv, NT, 3 * H, H, 0);
    attn_tc_kernel<<<dim3(NT / 128, NH), 256, ATTN_SMEM_BYTES>>>(pqkv, pctx);
    gemm_tc_kernel<64><<<dim3(H / 64, NT / 128), 256, GEMM_SMEM_64>>>(
        pctx, out_proj_w, out_proj_b, nullptr, nullptr, nullptr, pattn, NT, H, H, 0);
    gemm_tc_kernel<64><<<dim3(H / 64, NT / 128), 256, GEMM_SMEM_64>>>(
        pattn, post_w, post_b, ptout, nullptr, nullptr, out, NT, H, H, 2);
}